// round 14
// baseline (speedup 1.0000x reference)
#include <cuda_runtime.h>
#include <cuda_fp16.h>
#include <math.h>
#include <stdint.h>

#define T_TOK 2048
#define NH    32
#define NKV   8
#define HD    128
#define GQA   4
#define BM    128
#define BN    64
#define NTH   256          // 8 warps
#define ATTN_SCALE 0.08838834764831845f
#define CEXP2 0.1275187815175719f   // ATTN_SCALE * log2(e)

// ---- pre-converted fp16 copies of K/V, head-major ----
__device__ __half gK[(size_t)NKV * T_TOK * HD];
__device__ __half gV[(size_t)NKV * T_TOK * HD];

// smem: K stages x2 (16KB), V stages x2 (16KB) = 64KB
// Q staging (32KB, prologue only) aliases both V stages [32768, 65536).
#define S_K(s) ((s) * 16384)
#define S_V(s) (32768 + (s) * 16384)
#define SMEM_BYTES 65536

__device__ __forceinline__ uint32_t smem_u32(const void* p) {
    return (uint32_t)__cvta_generic_to_shared(p);
}
// swizzled byte offset of 16B chunk (row, chunk 0..15) in a [rows][256B] tile
__device__ __forceinline__ uint32_t sw_off(int row, int chunk) {
    return (uint32_t)(row * 256 + ((chunk ^ (row & 7)) << 4));
}
__device__ __forceinline__ void cp16(uint32_t dst, const void* src) {
    asm volatile("cp.async.cg.shared.global [%0], [%1], 16;" :: "r"(dst), "l"(src));
}
__device__ __forceinline__ void ldsm4(uint32_t (&r)[4], uint32_t a) {
    asm volatile("ldmatrix.sync.aligned.m8n8.x4.shared.b16 {%0,%1,%2,%3}, [%4];"
                 : "=r"(r[0]), "=r"(r[1]), "=r"(r[2]), "=r"(r[3]) : "r"(a));
}
__device__ __forceinline__ void ldsm4t(uint32_t (&r)[4], uint32_t a) {
    asm volatile("ldmatrix.sync.aligned.m8n8.x4.trans.shared.b16 {%0,%1,%2,%3}, [%4];"
                 : "=r"(r[0]), "=r"(r[1]), "=r"(r[2]), "=r"(r[3]) : "r"(a));
}
__device__ __forceinline__ void mma16816(float (&d)[4], const uint32_t (&a)[4],
                                         uint32_t b0, uint32_t b1) {
    asm volatile(
        "mma.sync.aligned.m16n8k16.row.col.f32.f16.f16.f32 "
        "{%0,%1,%2,%3}, {%4,%5,%6,%7}, {%8,%9}, {%0,%1,%2,%3};"
        : "+f"(d[0]), "+f"(d[1]), "+f"(d[2]), "+f"(d[3])
        : "r"(a[0]), "r"(a[1]), "r"(a[2]), "r"(a[3]), "r"(b0), "r"(b1));
}
// single-instruction pack: {lo=x, hi=y}
__device__ __forceinline__ uint32_t pack_f2(float x, float y) {
    __half2 hh = __float22half2_rn(make_float2(x, y));
    return *reinterpret_cast<uint32_t*>(&hh);
}

// ---- pre-pass: K/V fp32 -> fp16, head-major ----
__global__ __launch_bounds__(256)
void cvt_kernel(const float* __restrict__ k, const float* __restrict__ v) {
    const int NK4 = T_TOK * NKV * 32;    // float4 groups per tensor
    int idx = blockIdx.x * 256 + threadIdx.x;

    const float* src;
    __half* dst;
    if (idx < NK4) { src = k; dst = gK; }
    else if (idx < 2 * NK4) { idx -= NK4; src = v; dst = gV; }
    else return;

    int d4 = idx & 31;
    int hh = (idx >> 5) & 7;
    int t  = idx >> 8;
    float4 f = *reinterpret_cast<const float4*>(
        src + ((size_t)t * NKV + hh) * HD + d4 * 4);
    uint32_t w0 = pack_f2(f.x, f.y);
    uint32_t w1 = pack_f2(f.z, f.w);
    size_t o = ((size_t)hh * T_TOK + t) * HD + d4 * 4;
    *reinterpret_cast<uint2*>(dst + o) = make_uint2(w0, w1);
}

__global__ __launch_bounds__(NTH, 1)
void attn_mma_kernel(const float* __restrict__ q, float* __restrict__ out) {
    extern __shared__ char sm[];
    const uint32_t sB = smem_u32(sm);

    const int qt  = (int)gridDim.x - 1 - (int)blockIdx.x;  // heavy tiles first
    const int h   = blockIdx.y;
    const int kvh = h / GQA;
    const int q0  = qt * BM;
    const int nt  = (q0 + BM) / BN;     // = 2*qt+2, always >= 2

    const int tid  = threadIdx.x;
    const int lane = tid & 31;
    const int warp = tid >> 5;          // 0..7 -> rows [warp*16, +16)
    const int gid  = lane >> 2;
    const int tig  = lane & 3;

    const int rowA  = warp * 16 + (lane & 15);
    const int rowB0 = ((lane >> 4) << 3) + (lane & 7);    // 0..15
    const int rowV0 = ((lane >> 3) & 1) * 8 + (lane & 7); // 0..15
    const int cHi   = lane >> 4;          // A/V column selector
    const int cLo   = (lane >> 3) & 1;    // K column selector
    const int row0  = q0 + warp * 16 + gid;
    const int row1  = row0 + 8;

    // ---- loaders: [64 rows][16 chunks] = 1024 chunks, 4 per thread
    auto load_K = [&](int j) {
        int n0 = j * BN;
        uint32_t b = sB + S_K(j & 1);
        #pragma unroll
        for (int it = 0; it < 4; it++) {
            int idx = it * NTH + tid;
            int row = idx >> 4, ch = idx & 15;
            cp16(b + sw_off(row, ch),
                 gK + ((size_t)kvh * T_TOK + n0 + row) * HD + ch * 8);
        }
    };
    auto load_V = [&](int j) {
        int n0 = j * BN;
        uint32_t b = sB + S_V(j & 1);
        #pragma unroll
        for (int it = 0; it < 4; it++) {
            int idx = it * NTH + tid;
            int row = idx >> 4, ch = idx & 15;
            cp16(b + sw_off(row, ch),
                 gV + ((size_t)kvh * T_TOK + n0 + row) * HD + ch * 8);
        }
    };

    // ---- prologue ----
    load_K(0);
    asm volatile("cp.async.commit_group;");   // G1 = {K0}
    // convert Q (128 rows fp32) through scratch aliasing the V stages
    uint32_t qf[8][4];
    {
        const uint32_t stg = sB + 32768;    // 32KB scratch over V0+V1
        #pragma unroll
        for (int it = 0; it < 16; it++) {
            int idx = it * 32 + lane;       // 0..511 within warp
            int rl = idx >> 5, f4 = idx & 31;
            int row = warp * 16 + rl;
            float4 f = *reinterpret_cast<const float4*>(
                q + ((size_t)(q0 + row) * NH + h) * HD + f4 * 4);
            uint32_t w0 = pack_f2(f.x, f.y);
            uint32_t w1 = pack_f2(f.z, f.w);
            uint32_t off = sw_off(row, f4 >> 1) + (uint32_t)(f4 & 1) * 8;
            *reinterpret_cast<uint2*>(sm + 32768 + off) = make_uint2(w0, w1);
        }
        __syncwarp();
        #pragma unroll
        for (int kk = 0; kk < 8; kk++)
            ldsm4(qf[kk], stg + sw_off(rowA, 2 * kk + cHi));
    }
    __syncthreads();               // all warps done reading Q scratch
    load_V(0); load_K(1);
    asm volatile("cp.async.commit_group;");   // G2 = {V0, K1}
    asm volatile("cp.async.wait_group 1;");   // K0 ready
    __syncthreads();

    float o[16][4];
    #pragma unroll
    for (int t = 0; t < 16; t++)
        #pragma unroll
        for (int c = 0; c < 4; c++) o[t][c] = 0.f;
    float l0 = 0.f, l1 = 0.f;
    uint32_t pPrev[8][2];                 // P(kt-1) carried in registers

    // ---- softmax(kt): s -> pPrev, accumulate l  (mask on last two tiles)
    auto softmax = [&](float (&s)[8][4], int kt) {
        const bool diag = (kt >= nt - 2);
        const int n0 = kt * BN;
        #pragma unroll
        for (int t = 0; t < 8; t++) {
            int c0 = n0 + t * 8 + tig * 2;
            float p0 = exp2f(s[t][0] * CEXP2);
            float p1 = exp2f(s[t][1] * CEXP2);
            float p2 = exp2f(s[t][2] * CEXP2);
            float p3 = exp2f(s[t][3] * CEXP2);
            if (diag) {
                if (c0     > row0) p0 = 0.f;
                if (c0 + 1 > row0) p1 = 0.f;
                if (c0     > row1) p2 = 0.f;
                if (c0 + 1 > row1) p3 = 0.f;
            }
            l0 += p0 + p1;
            l1 += p2 + p3;
            pPrev[t][0] = pack_f2(p0, p1);
            pPrev[t][1] = pack_f2(p2, p3);
        }
    };

    // ---- peeled kt=0: GEMM1 only, K fragments pipelined
    {
        const uint32_t bK = sB + S_K(0);
        float s[8][4];
        #pragma unroll
        for (int t = 0; t < 8; t++)
            #pragma unroll
            for (int c = 0; c < 4; c++) s[t][c] = 0.f;

        uint32_t kc[4][4];
        #pragma unroll
        for (int j = 0; j < 4; j++)
            ldsm4(kc[j], bK + sw_off(rowB0 + 16 * j, cLo));
        #pragma unroll
        for (int i = 0; i < 8; i++) {
            uint32_t kn[4][4];
            if (i < 7) {
                #pragma unroll
                for (int j = 0; j < 4; j++)
                    ldsm4(kn[j], bK + sw_off(rowB0 + 16 * j, 2 * (i + 1) + cLo));
            }
            #pragma unroll
            for (int j = 0; j < 4; j++) {
                mma16816(s[2 * j],     qf[i], kc[j][0], kc[j][1]);
                mma16816(s[2 * j + 1], qf[i], kc[j][2], kc[j][3]);
            }
            if (i < 7) {
                #pragma unroll
                for (int j = 0; j < 4; j++)
                    #pragma unroll
                    for (int r = 0; r < 4; r++) kc[j][r] = kn[j][r];
            }
        }
        softmax(s, 0);
    }

    // ---- main loop: iter kt = GEMM1(kt) + GEMM2(kt-1), fragments pipelined
    for (int kt = 1; kt < nt; kt++) {
        asm volatile("cp.async.wait_group 0;");
        __syncthreads();      // acquire K(kt),V(kt-1); release old stages

        // early issue: full-iteration lead for next tiles
        if (kt + 1 < nt) load_K(kt + 1);
        load_V(kt);
        asm volatile("cp.async.commit_group;");

        const uint32_t bK = sB + S_K(kt & 1);
        const uint32_t bV = sB + S_V((kt - 1) & 1);

        float s[8][4];
        #pragma unroll
        for (int t = 0; t < 8; t++)
            #pragma unroll
            for (int c = 0; c < 4; c++) s[t][c] = 0.f;

        // preload step-0 fragments: 4 K + 4 V
        uint32_t kc[4][4], vc[4][4];
        #pragma unroll
        for (int j = 0; j < 4; j++) {
            ldsm4(kc[j], bK + sw_off(rowB0 + 16 * j, cLo));
            ldsm4t(vc[j], bV + sw_off(16 * j + rowV0, cHi));
        }

        #pragma unroll
        for (int i = 0; i < 8; i++) {
            // issue loads for step i+1
            uint32_t kn[4][4], vn[4][4];
            if (i < 7) {
                #pragma unroll
                for (int j = 0; j < 4; j++) {
                    ldsm4(kn[j], bK + sw_off(rowB0 + 16 * j, 2 * (i + 1) + cLo));
                    ldsm4t(vn[j], bV + sw_off(16 * j + rowV0, 2 * (i + 1) + cHi));
                }
            }
            // GEMM1 step i: S k-chunk i
            #pragma unroll
            for (int j = 0; j < 4; j++) {
                mma16816(s[2 * j],     qf[i], kc[j][0], kc[j][1]);
                mma16816(s[2 * j + 1], qf[i], kc[j][2], kc[j][3]);
            }
            // GEMM2 step i: O d-chunk i, accumulate over 4 kv-row chunks
            #pragma unroll
            for (int j = 0; j < 4; j++) {
                uint32_t aF[4] = {pPrev[2 * j][0],     pPrev[2 * j][1],
                                  pPrev[2 * j + 1][0], pPrev[2 * j + 1][1]};
                mma16816(o[2 * i],     aF, vc[j][0], vc[j][1]);
                mma16816(o[2 * i + 1], aF, vc[j][2], vc[j][3]);
            }
            if (i < 7) {
                #pragma unroll
                for (int j = 0; j < 4; j++)
                    #pragma unroll
                    for (int r = 0; r < 4; r++) {
                        kc[j][r] = kn[j][r];
                        vc[j][r] = vn[j][r];
                    }
            }
        }
        softmax(s, kt);
    }

    // ---- drain: O += P(nt-1) @ V(nt-1)
    asm volatile("cp.async.wait_group 0;");
    __syncthreads();
    {
        const uint32_t bV = sB + S_V((nt - 1) & 1);
        #pragma unroll
        for (int i = 0; i < 8; i++) {
            #pragma unroll
            for (int j = 0; j < 4; j++) {
                uint32_t vh[4];
                ldsm4t(vh, bV + sw_off(16 * j + rowV0, 2 * i + cHi));
                uint32_t aF[4] = {pPrev[2 * j][0],     pPrev[2 * j][1],
                                  pPrev[2 * j + 1][0], pPrev[2 * j + 1][1]};
                mma16816(o[2 * i],     aF, vh[0], vh[1]);
                mma16816(o[2 * i + 1], aF, vh[2], vh[3]);
            }
        }
    }

    // ---- epilogue: reduce row sums over the quad, normalize, store
    l0 += __shfl_xor_sync(0xffffffffu, l0, 1);
    l0 += __shfl_xor_sync(0xffffffffu, l0, 2);
    l1 += __shfl_xor_sync(0xffffffffu, l1, 1);
    l1 += __shfl_xor_sync(0xffffffffu, l1, 2);
    float inv0 = 1.f / l0, inv1 = 1.f / l1;
    #pragma unroll
    for (int t = 0; t < 16; t++) {
        int d = t * 8 + tig * 2;
        float2 w0 = make_float2(o[t][0] * inv0, o[t][1] * inv0);
        float2 w1 = make_float2(o[t][2] * inv1, o[t][3] * inv1);
        *reinterpret_cast<float2*>(&out[(size_t)row0 * (NH * HD) + h * HD + d]) = w0;
        *reinterpret_cast<float2*>(&out[(size_t)row1 * (NH * HD) + h * HD + d]) = w1;
    }
}

extern "C" void kernel_launch(void* const* d_in, const int* in_sizes, int n_in,
                              void* d_out, int out_size) {
    const float* q = (const float*)d_in[0];
    const float* k = (const float*)d_in[1];
    const float* v = (const float*)d_in[2];
    float* out = (float*)d_out;

    const int NK4 = T_TOK * NKV * 32;
    cvt_kernel<<<(2 * NK4 + 255) / 256, 256>>>(k, v);

    cudaFuncSetAttribute(attn_mma_kernel,
                         cudaFuncAttributeMaxDynamicSharedMemorySize, SMEM_BYTES);
    dim3 grid(T_TOK / BM, NH);
    attn_mma_kernel<<<grid, NTH, SMEM_BYTES>>>(q, out);
}

// round 15
// speedup vs baseline: 1.1328x; 1.1328x over previous
#include <cuda_runtime.h>
#include <cuda.h>
#include <cuda_fp16.h>
#include <math.h>
#include <stdint.h>

#define T_TOK 2048
#define NH    32
#define NKV   8
#define HD    128
#define GQA   4
#define BM    64
#define BN    64
#define NTH   128          // 4 warps
#define ATTN_SCALE 0.08838834764831845f
#define CEXP2 0.1275187815175719f   // ATTN_SCALE * log2(e)

// ---- pre-converted fp16 copies of K/V, head-major ----
__device__ __half gK[(size_t)NKV * T_TOK * HD];
__device__ __half gV[(size_t)NKV * T_TOK * HD];

// smem: 3 stages x (K 16KB + V 16KB) = 96KB, mbarriers at 98304
#define STG_BYTES 32768
#define MB_OFF    98304
#define SMEM_BYTES 98432

__device__ __forceinline__ uint32_t smem_u32(const void* p) {
    return (uint32_t)__cvta_generic_to_shared(p);
}
// swizzled byte offset of 16B chunk (row, chunk 0..15) inside a 16KB tile
// stored as two [64 rows][128B] SW128 half-tiles (TMA layout)
__device__ __forceinline__ uint32_t swT(int row, int c) {
    return (uint32_t)(((c >> 3) << 13) + (row << 7) + ((((c & 7) ^ (row & 7))) << 4));
}
__device__ __forceinline__ void ldsm4(uint32_t (&r)[4], uint32_t a) {
    asm volatile("ldmatrix.sync.aligned.m8n8.x4.shared.b16 {%0,%1,%2,%3}, [%4];"
                 : "=r"(r[0]), "=r"(r[1]), "=r"(r[2]), "=r"(r[3]) : "r"(a));
}
__device__ __forceinline__ void ldsm4t(uint32_t (&r)[4], uint32_t a) {
    asm volatile("ldmatrix.sync.aligned.m8n8.x4.trans.shared.b16 {%0,%1,%2,%3}, [%4];"
                 : "=r"(r[0]), "=r"(r[1]), "=r"(r[2]), "=r"(r[3]) : "r"(a));
}
__device__ __forceinline__ void mma16816(float (&d)[4], const uint32_t (&a)[4],
                                         uint32_t b0, uint32_t b1) {
    asm volatile(
        "mma.sync.aligned.m16n8k16.row.col.f32.f16.f16.f32 "
        "{%0,%1,%2,%3}, {%4,%5,%6,%7}, {%8,%9}, {%0,%1,%2,%3};"
        : "+f"(d[0]), "+f"(d[1]), "+f"(d[2]), "+f"(d[3])
        : "r"(a[0]), "r"(a[1]), "r"(a[2]), "r"(a[3]), "r"(b0), "r"(b1));
}
__device__ __forceinline__ uint32_t pack_f2(float x, float y) {
    __half2 hh = __float22half2_rn(make_float2(x, y));
    return *reinterpret_cast<uint32_t*>(&hh);
}
__device__ __forceinline__ void mbar_init(uint32_t a, uint32_t cnt) {
    asm volatile("mbarrier.init.shared.b64 [%0], %1;" :: "r"(a), "r"(cnt) : "memory");
}
__device__ __forceinline__ void mbar_arrive(uint32_t a) {
    asm volatile("mbarrier.arrive.shared.b64 _, [%0];" :: "r"(a) : "memory");
}
__device__ __forceinline__ void mbar_expect_tx(uint32_t a, uint32_t tx) {
    asm volatile("mbarrier.arrive.expect_tx.shared.b64 _, [%0], %1;"
                 :: "r"(a), "r"(tx) : "memory");
}
__device__ __forceinline__ void mwait(uint32_t mbar, int phase) {
    asm volatile(
        "{\n\t.reg .pred P;\n"
        "W1_%=:\n\t"
        "mbarrier.try_wait.parity.acquire.cta.shared::cta.b64 P, [%0], %1, 10000000;\n\t"
        "@P bra W2_%=;\n\t"
        "bra W1_%=;\n"
        "W2_%=:\n\t}"
        :: "r"(mbar), "r"((uint32_t)phase) : "memory");
}
__device__ __forceinline__ void tma3d(uint32_t dst, const CUtensorMap* m,
                                      int x, int y, int z, uint32_t mbar) {
    asm volatile(
        "cp.async.bulk.tensor.3d.shared::cta.global.tile.mbarrier::complete_tx::bytes "
        "[%0], [%1, {%2, %3, %4}], [%5];"
        :: "r"(dst), "l"(m), "r"(x), "r"(y), "r"(z), "r"(mbar) : "memory");
}

// ---- pre-pass: K/V fp32 -> fp16, head-major ----
__global__ __launch_bounds__(256)
void cvt_kernel(const float* __restrict__ k, const float* __restrict__ v) {
    const int NK4 = T_TOK * NKV * 32;
    int idx = blockIdx.x * 256 + threadIdx.x;
    const float* src;
    __half* dst;
    if (idx < NK4) { src = k; dst = gK; }
    else if (idx < 2 * NK4) { idx -= NK4; src = v; dst = gV; }
    else return;
    int d4 = idx & 31;
    int hh = (idx >> 5) & 7;
    int t  = idx >> 8;
    float4 f = *reinterpret_cast<const float4*>(
        src + ((size_t)t * NKV + hh) * HD + d4 * 4);
    uint32_t w0 = pack_f2(f.x, f.y);
    uint32_t w1 = pack_f2(f.z, f.w);
    size_t o = ((size_t)hh * T_TOK + t) * HD + d4 * 4;
    *reinterpret_cast<uint2*>(dst + o) = make_uint2(w0, w1);
}

__global__ __launch_bounds__(NTH, 2)
void attn_mma_kernel(const __grid_constant__ CUtensorMap mapK,
                     const __grid_constant__ CUtensorMap mapV,
                     const float* __restrict__ q, float* __restrict__ out) {
    extern __shared__ char sm[];
    const uint32_t sB = smem_u32(sm);

    const int qt  = (int)gridDim.x - 1 - (int)blockIdx.x;  // heavy tiles first
    const int h   = blockIdx.y;
    const int kvh = h / GQA;
    const int q0  = qt * BM;
    const int nt  = qt + 1;

    const int tid  = threadIdx.x;
    const int lane = tid & 31;
    const int warp = tid >> 5;          // 0..3 -> rows [warp*16, +16)
    const int gid  = lane >> 2;
    const int tig  = lane & 3;

    const int rowB0 = ((lane >> 4) << 3) + (lane & 7);    // 0..15
    const int rowV0 = ((lane >> 3) & 1) * 8 + (lane & 7); // 0..15
    const int cHi   = lane >> 4;          // V column selector
    const int cLo   = (lane >> 3) & 1;    // K column selector
    const int row0  = q0 + warp * 16 + gid;
    const int row1  = row0 + 8;

    auto mbF = [&](int s) { return sB + MB_OFF + (uint32_t)s * 16; };
    auto mbE = [&](int s) { return sB + MB_OFF + (uint32_t)s * 16 + 8; };

    // ---- init mbarriers ----
    if (tid == 0) {
        #pragma unroll
        for (int s = 0; s < 3; s++) {
            mbar_init(mbF(s), 1);    // producer expect_tx arrive
            mbar_init(mbE(s), 4);    // one arrive per warp
        }
        asm volatile("fence.proxy.async.shared::cta;" ::: "memory");
    }
    __syncthreads();   // only CTA-wide barrier in the kernel

    // ---- producer: issue K+V tile j into stage s (single thread)
    auto issue_tile = [&](int j, int s) {
        uint32_t full = mbF(s);
        mbar_expect_tx(full, 2 * STG_BYTES / 2);     // 32768 bytes
        uint32_t base = sB + (uint32_t)s * STG_BYTES;
        tma3d(base,         &mapK,  0, j * BN, kvh, full);
        tma3d(base + 8192,  &mapK, 64, j * BN, kvh, full);
        tma3d(base + 16384, &mapV,  0, j * BN, kvh, full);
        tma3d(base + 24576, &mapV, 64, j * BN, kvh, full);
    };
    if (tid == 0) {
        int npre = nt < 3 ? nt : 3;
        for (int j = 0; j < npre; j++) issue_tile(j, j);
    }

    // ---- Q fragments: LDG fp32 -> fp16x2 directly into registers
    uint32_t qf[8][4];
    {
        const float* p0 = q + ((size_t)row0 * NH + h) * HD + tig * 2;
        const float* p1 = q + ((size_t)row1 * NH + h) * HD + tig * 2;
        #pragma unroll
        for (int kk = 0; kk < 8; kk++) {
            int d0 = kk * 16;
            float2 x0 = *reinterpret_cast<const float2*>(p0 + d0);
            float2 x1 = *reinterpret_cast<const float2*>(p1 + d0);
            float2 x2 = *reinterpret_cast<const float2*>(p0 + d0 + 8);
            float2 x3 = *reinterpret_cast<const float2*>(p1 + d0 + 8);
            qf[kk][0] = pack_f2(x0.x, x0.y);
            qf[kk][1] = pack_f2(x1.x, x1.y);
            qf[kk][2] = pack_f2(x2.x, x2.y);
            qf[kk][3] = pack_f2(x3.x, x3.y);
        }
    }

    float o[16][4];
    #pragma unroll
    for (int t = 0; t < 16; t++)
        #pragma unroll
        for (int c = 0; c < 4; c++) o[t][c] = 0.f;
    float l0 = 0.f, l1 = 0.f;
    uint32_t pPrev[8][2];

    auto softmax = [&](float (&s)[8][4], int kt) {
        const bool diag = (kt == nt - 1);
        const int n0 = kt * BN;
        #pragma unroll
        for (int t = 0; t < 8; t++) {
            int c0 = n0 + t * 8 + tig * 2;
            float p0 = exp2f(s[t][0] * CEXP2);
            float p1 = exp2f(s[t][1] * CEXP2);
            float p2 = exp2f(s[t][2] * CEXP2);
            float p3 = exp2f(s[t][3] * CEXP2);
            if (diag) {
                if (c0     > row0) p0 = 0.f;
                if (c0 + 1 > row0) p1 = 0.f;
                if (c0     > row1) p2 = 0.f;
                if (c0 + 1 > row1) p3 = 0.f;
            }
            l0 += p0 + p1;
            l1 += p2 + p3;
            pPrev[t][0] = pack_f2(p0, p1);
            pPrev[t][1] = pack_f2(p2, p3);
        }
    };

    int kS = 0, kP = 0;     // consumer cursor for tile kt
    int pP = 0;             // producer phase over empty barriers

    // ---- peeled kt=0: GEMM1 only, K fragments pipelined
    {
        mwait(mbF(0), 0);
        const uint32_t bK = sB;
        float s[8][4];
        #pragma unroll
        for (int t = 0; t < 8; t++)
            #pragma unroll
            for (int c = 0; c < 4; c++) s[t][c] = 0.f;

        uint32_t kc[4][4];
        #pragma unroll
        for (int j = 0; j < 4; j++)
            ldsm4(kc[j], bK + swT(rowB0 + 16 * j, cLo));
        #pragma unroll
        for (int i = 0; i < 8; i++) {
            uint32_t kn[4][4];
            if (i < 7) {
                #pragma unroll
                for (int j = 0; j < 4; j++)
                    ldsm4(kn[j], bK + swT(rowB0 + 16 * j, 2 * (i + 1) + cLo));
            }
            #pragma unroll
            for (int j = 0; j < 4; j++) {
                mma16816(s[2 * j],     qf[i], kc[j][0], kc[j][1]);
                mma16816(s[2 * j + 1], qf[i], kc[j][2], kc[j][3]);
            }
            if (i < 7) {
                #pragma unroll
                for (int j = 0; j < 4; j++)
                    #pragma unroll
                    for (int r = 0; r < 4; r++) kc[j][r] = kn[j][r];
            }
        }
        softmax(s, 0);
        kS = 1;
    }

    // ---- main loop: iter kt = GEMM1(kt) + GEMM2(kt-1), no CTA barriers
    for (int kt = 1; kt < nt; kt++) {
        mwait(mbF(kS), kP);
        const int vS = (kS == 0) ? 2 : kS - 1;
        const uint32_t bK = sB + (uint32_t)kS * STG_BYTES;
        const uint32_t bV = sB + (uint32_t)vS * STG_BYTES + 16384;

        float s[8][4];
        #pragma unroll
        for (int t = 0; t < 8; t++)
            #pragma unroll
            for (int c = 0; c < 4; c++) s[t][c] = 0.f;

        uint32_t kc[4][4], vc[4][4];
        #pragma unroll
        for (int j = 0; j < 4; j++) {
            ldsm4(kc[j], bK + swT(rowB0 + 16 * j, cLo));
            ldsm4t(vc[j], bV + swT(16 * j + rowV0, cHi));
        }

        #pragma unroll
        for (int i = 0; i < 8; i++) {
            uint32_t kn[4][4], vn[4][4];
            if (i < 7) {
                #pragma unroll
                for (int j = 0; j < 4; j++) {
                    ldsm4(kn[j], bK + swT(rowB0 + 16 * j, 2 * (i + 1) + cLo));
                    ldsm4t(vn[j], bV + swT(16 * j + rowV0, 2 * (i + 1) + cHi));
                }
            }
            #pragma unroll
            for (int j = 0; j < 4; j++) {
                mma16816(s[2 * j],     qf[i], kc[j][0], kc[j][1]);
                mma16816(s[2 * j + 1], qf[i], kc[j][2], kc[j][3]);
            }
            #pragma unroll
            for (int j = 0; j < 4; j++) {
                uint32_t aF[4] = {pPrev[2 * j][0],     pPrev[2 * j][1],
                                  pPrev[2 * j + 1][0], pPrev[2 * j + 1][1]};
                mma16816(o[2 * i],     aF, vc[j][0], vc[j][1]);
                mma16816(o[2 * i + 1], aF, vc[j][2], vc[j][3]);
            }
            if (i < 7) {
                #pragma unroll
                for (int j = 0; j < 4; j++)
                    #pragma unroll
                    for (int r = 0; r < 4; r++) {
                        kc[j][r] = kn[j][r];
                        vc[j][r] = vn[j][r];
                    }
            }
        }

        // release stage vS (K(kt-1)+V(kt-1) fully consumed)
        if (lane == 0) mbar_arrive(mbE(vS));
        // producer: refill stage vS with tile kt+2
        if (kt + 2 < nt) {
            if (tid == 0) {
                mwait(mbE(vS), pP);
                issue_tile(kt + 2, vS);
            }
            if (vS == 2) pP ^= 1;
        }
        softmax(s, kt);
        if (++kS == 3) { kS = 0; kP ^= 1; }
    }

    // ---- drain: O += P(nt-1) @ V(nt-1)
    {
        const int vS = (kS == 0) ? 2 : kS - 1;
        const uint32_t bV = sB + (uint32_t)vS * STG_BYTES + 16384;
        #pragma unroll
        for (int i = 0; i < 8; i++) {
            #pragma unroll
            for (int j = 0; j < 4; j++) {
                uint32_t vh[4];
                ldsm4t(vh, bV + swT(16 * j + rowV0, 2 * i + cHi));
                uint32_t aF[4] = {pPrev[2 * j][0],     pPrev[2 * j][1],
                                  pPrev[2 * j + 1][0], pPrev[2 * j + 1][1]};
                mma16816(o[2 * i],     aF, vh[0], vh[1]);
                mma16816(o[2 * i + 1], aF, vh[2], vh[3]);
            }
        }
    }

    // ---- epilogue
    l0 += __shfl_xor_sync(0xffffffffu, l0, 1);
    l0 += __shfl_xor_sync(0xffffffffu, l0, 2);
    l1 += __shfl_xor_sync(0xffffffffu, l1, 1);
    l1 += __shfl_xor_sync(0xffffffffu, l1, 2);
    float inv0 = 1.f / l0, inv1 = 1.f / l1;
    #pragma unroll
    for (int t = 0; t < 16; t++) {
        int d = t * 8 + tig * 2;
        float2 w0 = make_float2(o[t][0] * inv0, o[t][1] * inv0);
        float2 w1 = make_float2(o[t][2] * inv1, o[t][3] * inv1);
        *reinterpret_cast<float2*>(&out[(size_t)row0 * (NH * HD) + h * HD + d]) = w0;
        *reinterpret_cast<float2*>(&out[(size_t)row1 * (NH * HD) + h * HD + d]) = w1;
    }
}

typedef CUresult (*PFN_encode)(
    CUtensorMap*, CUtensorMapDataType, cuuint32_t, void*,
    const cuuint64_t*, const cuuint64_t*, const cuuint32_t*, const cuuint32_t*,
    CUtensorMapInterleave, CUtensorMapSwizzle, CUtensorMapL2promotion,
    CUtensorMapFloatOOBfill);

extern "C" void kernel_launch(void* const* d_in, const int* in_sizes, int n_in,
                              void* d_out, int out_size) {
    const float* q = (const float*)d_in[0];
    const float* k = (const float*)d_in[1];
    const float* v = (const float*)d_in[2];
    float* out = (float*)d_out;

    const int NK4 = T_TOK * NKV * 32;
    cvt_kernel<<<(2 * NK4 + 255) / 256, 256>>>(k, v);

    // build TMA descriptors for gK / gV
    PFN_encode encode = nullptr;
    cudaDriverEntryPointQueryResult qres;
    cudaGetDriverEntryPoint("cuTensorMapEncodeTiled", (void**)&encode,
                            cudaEnableDefault, &qres);
    void *pk = nullptr, *pv = nullptr;
    cudaGetSymbolAddress(&pk, gK);
    cudaGetSymbolAddress(&pv, gV);

    CUtensorMap mk, mv;
    cuuint64_t dims[3]    = {HD, T_TOK, NKV};
    cuuint64_t strides[2] = {HD * 2, (cuuint64_t)T_TOK * HD * 2};
    cuuint32_t box[3]     = {64, BN, 1};
    cuuint32_t estr[3]    = {1, 1, 1};
    encode(&mk, CU_TENSOR_MAP_DATA_TYPE_UINT16, 3, pk, dims, strides, box, estr,
           CU_TENSOR_MAP_INTERLEAVE_NONE, CU_TENSOR_MAP_SWIZZLE_128B,
           CU_TENSOR_MAP_L2_PROMOTION_L2_128B, CU_TENSOR_MAP_FLOAT_OOB_FILL_NONE);
    encode(&mv, CU_TENSOR_MAP_DATA_TYPE_UINT16, 3, pv, dims, strides, box, estr,
           CU_TENSOR_MAP_INTERLEAVE_NONE, CU_TENSOR_MAP_SWIZZLE_128B,
           CU_TENSOR_MAP_L2_PROMOTION_L2_128B, CU_TENSOR_MAP_FLOAT_OOB_FILL_NONE);

    cudaFuncSetAttribute(attn_mma_kernel,
                         cudaFuncAttributeMaxDynamicSharedMemorySize, SMEM_BYTES);
    dim3 grid(T_TOK / BM, NH);
    attn_mma_kernel<<<grid, NTH, SMEM_BYTES>>>(mk, mv, q, out);
}